// round 14
// baseline (speedup 1.0000x reference)
#include <cuda_runtime.h>

#define BATCH   262144
#define NIND    32
#define NDEP    16
#define EPSV    1e-7f
#define ITERS   2

typedef unsigned long long u64;

// ---- packed f32x2 helpers (Blackwell sm_103a) ----
__device__ __forceinline__ u64 pack2(float a, float b) {
    u64 r; asm("mov.b64 %0, {%1, %2};" : "=l"(r) : "f"(a), "f"(b)); return r;
}
__device__ __forceinline__ u64 dup2(float a) {
    u64 r; asm("mov.b64 %0, {%1, %1};" : "=l"(r) : "f"(a)); return r;
}
__device__ __forceinline__ void unpack2(u64 v, float &a, float &b) {
    asm("mov.b64 {%0, %1}, %2;" : "=f"(a), "=f"(b) : "l"(v));
}
__device__ __forceinline__ u64 ffma2(u64 a, u64 b, u64 c) {
    u64 d; asm("fma.rn.f32x2 %0, %1, %2, %3;" : "=l"(d) : "l"(a), "l"(b), "l"(c));
    return d;
}
__device__ __forceinline__ u64 mul2(u64 a, u64 b) {
    u64 d; asm("mul.rn.f32x2 %0, %1, %2;" : "=l"(d) : "l"(a), "l"(b));
    return d;
}
__device__ __forceinline__ float frcp(float x) {
    float r; asm("rcp.approx.f32 %0, %1;" : "=f"(r) : "f"(x)); return r;
}

// Pre-transformed weights: row-paired u64 for direct f32x2 operands.
struct CWeights {
    ulonglong2 W2[2 * NIND][4];   // [k][q2]: rows (4q2..4q2+3) paired; k<32->Bmat, else Theta
    ulonglong2 L2[NIND][4];       // Lam
    ulonglong2 Off2[NDEP][4];     // column j, rows paired; +Gamma off-diag, 0 diag
    u64 Gd2[8];                   // (1+eps - Gamma_ii) pairs
    u64 Ups2[8];
};

__device__ CWeights g_scratch;    // written by prep kernel
__constant__ CWeights cw;         // copied from g_scratch before main kernel

// ---- prep kernel: transform raw weights into g_scratch layout ----
__global__ void prep_kernel(const float* __restrict__ Ups, const float* __restrict__ Bm,
                            const float* __restrict__ Th,  const float* __restrict__ Ga,
                            const float* __restrict__ La)
{
    const int tid = threadIdx.x;
    for (int idx = tid; idx < 2 * NIND * 8; idx += 64) {
        int k = idx >> 3, j2 = idx & 7;
        int r0 = 2 * j2, r1 = r0 + 1;
        float w0, w1;
        if (k < NIND) { w0 = Bm[r0 * NIND + k];          w1 = Bm[r1 * NIND + k]; }
        else          { w0 = Th[r0 * NIND + (k - NIND)]; w1 = Th[r1 * NIND + (k - NIND)]; }
        ((u64*)&g_scratch.W2[k][0])[j2] = pack2(w0, w1);
    }
    for (int idx = tid; idx < NIND * 8; idx += 64) {
        int k = idx >> 3, j2 = idx & 7;
        ((u64*)&g_scratch.L2[k][0])[j2] =
            pack2(La[(2 * j2) * NIND + k], La[(2 * j2 + 1) * NIND + k]);
    }
    for (int idx = tid; idx < NDEP * 8; idx += 64) {
        int j = idx >> 3, i2 = idx & 7;
        int i0 = 2 * i2, i1 = i0 + 1;
        float v0 = (i0 == j) ? 0.0f : Ga[i0 * NDEP + j];
        float v1 = (i1 == j) ? 0.0f : Ga[i1 * NDEP + j];
        ((u64*)&g_scratch.Off2[j][0])[i2] = pack2(v0, v1);
    }
    if (tid < 8) {
        g_scratch.Ups2[tid] = pack2(Ups[2 * tid], Ups[2 * tid + 1]);
        g_scratch.Gd2[tid]  = pack2(1.0f + EPSV - Ga[(2 * tid) * NDEP + 2 * tid],
                                    1.0f + EPSV - Ga[(2 * tid + 1) * NDEP + 2 * tid + 1]);
    }
}

#define S64  33    // u64 stride per staged row (odd -> balanced banks)
#define TPB  128   // threads per block, one element each

// ONE batch element per thread (R8 shape: lb(128,5), ~34% occ).
// THREE-WAY port split (calibrated: LDC.128=2cyc/SM, LDS.128=4cyc/SM,
// LDG broadcast ~1.8cyc/SM on the L1tex pipe):
//   constant port: W2 (+Ups/Gd)     256 LDC/thread  -> ~15us floor
//   L1tex (__ldg): L2 + Off2        256 LDG/thread  -> ~15us floor (L1-hot)
//   smem crossbar: x values only    64 LDS.64       -> ~4us
//   fma pipe:                                        ~15us
// x staged PRE-DUPLICATED as (x,x) u64 -> LDS.64 replaces LDS.32+2MOV.
__global__ __launch_bounds__(TPB, 5)
void clefo_kernel(const float* __restrict__ X, const float* __restrict__ Z,
                  const CWeights* __restrict__ gw,
                  float* __restrict__ out)
{
    __shared__ u64 sStage[TPB * S64];   // one block-slab of X or Z, duplicated pairs

    const int tid = threadIdx.x;
    const size_t base = (size_t)blockIdx.x * TPB;

    // ---- stage X slab: coalesced float4 reads -> duplicated u64 pairs ----
    {
        const float4* src = (const float4*)(X + base * NIND);
#pragma unroll
        for (int i = 0; i < 8; ++i) {
            int idx = tid + TPB * i;                 // float4 index in slab
            float4 v = src[idx];
            u64* d = &sStage[(idx >> 3) * S64 + ((idx & 7) << 2)];
            d[0] = pack2(v.x, v.x); d[1] = pack2(v.y, v.y);
            d[2] = pack2(v.z, v.z); d[3] = pack2(v.w, v.w);
        }
    }
    __syncthreads();

    const u64* row = &sStage[tid * S64];

    // ---- Phase 1a: X-loop  (rhs += Bm*x ; d = La*x), rows packed in pairs
    u64 rhs[8], dd[8];
#pragma unroll
    for (int q = 0; q < 8; ++q) { rhs[q] = cw.Ups2[q]; dd[q] = 0ull; }

#pragma unroll
    for (int k = 0; k < NIND; ++k) {
        u64 xd = row[k];                              // LDS.64, already (x,x)
#pragma unroll
        for (int q2 = 0; q2 < 4; ++q2) {
            ulonglong2 w = cw.W2[k][q2];              // constant port
            rhs[2 * q2]     = ffma2(xd, w.x, rhs[2 * q2]);
            rhs[2 * q2 + 1] = ffma2(xd, w.y, rhs[2 * q2 + 1]);
            ulonglong2 l = __ldg(&gw->L2[k][q2]);     // L1tex pipe (parallel)
            dd[2 * q2]      = ffma2(xd, l.x, dd[2 * q2]);
            dd[2 * q2 + 1]  = ffma2(xd, l.y, dd[2 * q2 + 1]);
        }
    }
    __syncthreads();

    // ---- stage Z slab (reuse buffer) ----
    {
        const float4* src = (const float4*)(Z + base * NIND);
#pragma unroll
        for (int i = 0; i < 8; ++i) {
            int idx = tid + TPB * i;
            float4 v = src[idx];
            u64* d = &sStage[(idx >> 3) * S64 + ((idx & 7) << 2)];
            d[0] = pack2(v.x, v.x); d[1] = pack2(v.y, v.y);
            d[2] = pack2(v.z, v.z); d[3] = pack2(v.w, v.w);
        }
    }
    __syncthreads();

    // ---- Phase 1b: Z-loop  (rhs += Theta*z)
#pragma unroll
    for (int kz = 0; kz < NIND; ++kz) {
        int k = NIND + kz;
        u64 xd = row[kz];
#pragma unroll
        for (int q2 = 0; q2 < 4; ++q2) {
            ulonglong2 w = cw.W2[k][q2];
            rhs[2 * q2]     = ffma2(xd, w.x, rhs[2 * q2]);
            rhs[2 * q2 + 1] = ffma2(xd, w.y, rhs[2 * q2 + 1]);
        }
    }

    // ---- Phase 2: Dg_i = (1+eps - Gamma_ii) - d_i ; inv = 1/Dg ; y0 = inv*rhs
    u64 inv[8], y[8];
#pragma unroll
    for (int q = 0; q < 8; ++q) {
        float g0, g1; unpack2(cw.Gd2[q], g0, g1);
        float d0, d1; unpack2(dd[q], d0, d1);
        inv[q] = pack2(frcp(g0 - d0), frcp(g1 - d1));
        y[q]   = mul2(inv[q], rhs[q]);
    }

    // ---- Phase 3: Neumann iterations  acc = rhs + GammaOff*y ; y = inv (*) acc
    // Off2 via __ldg -> L1tex pipe, constant port stays free for nothing else.
#pragma unroll
    for (int it = 0; it < ITERS; ++it) {
        u64 acc[8];
#pragma unroll
        for (int q = 0; q < 8; ++q) acc[q] = rhs[q];
#pragma unroll
        for (int j = 0; j < NDEP; ++j) {
            float a0, a1; unpack2(y[j >> 1], a0, a1);
            u64 yd = dup2((j & 1) ? a1 : a0);
#pragma unroll
            for (int q2 = 0; q2 < 4; ++q2) {
                ulonglong2 o = __ldg(&gw->Off2[j][q2]);
                acc[2 * q2]     = ffma2(yd, o.x, acc[2 * q2]);
                acc[2 * q2 + 1] = ffma2(yd, o.y, acc[2 * q2 + 1]);
            }
        }
#pragma unroll
        for (int q = 0; q < 8; ++q) y[q] = mul2(inv[q], acc[q]);
    }

    // ---- Store: row-packed pairs are already in output order -> STG.128
    ulonglong2* ov = (ulonglong2*)(out + (base + tid) * NDEP);
#pragma unroll
    for (int q = 0; q < 4; ++q) ov[q] = make_ulonglong2(y[2 * q], y[2 * q + 1]);
}

extern "C" void kernel_launch(void* const* d_in, const int* in_sizes, int n_in,
                              void* d_out, int out_size)
{
    const float* X  = (const float*)d_in[0];
    const float* Z  = (const float*)d_in[1];
    const float* Up = (const float*)d_in[2];
    const float* Bm = (const float*)d_in[3];
    const float* Th = (const float*)d_in[4];
    const float* Ga = (const float*)d_in[5];
    const float* La = (const float*)d_in[6];
    float* out = (float*)d_out;

    // 1) transform weights into device scratch
    prep_kernel<<<1, 64>>>(Up, Bm, Th, Ga, La);

    // 2) copy transformed weights into the constant bank (D2D, capturable)
    void* sp = nullptr;
    cudaGetSymbolAddress(&sp, g_scratch);
    cudaMemcpyToSymbolAsync(cw, sp, sizeof(CWeights), 0,
                            cudaMemcpyDeviceToDevice, 0);

    // 3) main kernel: one element per thread
    const int blocks = BATCH / TPB;
    clefo_kernel<<<blocks, TPB>>>(X, Z, (const CWeights*)sp, out);
}

// round 15
// speedup vs baseline: 1.5965x; 1.5965x over previous
#include <cuda_runtime.h>

#define BATCH   262144
#define NIND    32
#define NDEP    16
#define EPSV    1e-7f
#define ITERS   2

typedef unsigned long long u64;

// ---- packed f32x2 helpers (Blackwell sm_103a) ----
__device__ __forceinline__ u64 pack2(float a, float b) {
    u64 r; asm("mov.b64 %0, {%1, %2};" : "=l"(r) : "f"(a), "f"(b)); return r;
}
__device__ __forceinline__ u64 dup2(float a) {
    u64 r; asm("mov.b64 %0, {%1, %1};" : "=l"(r) : "f"(a)); return r;
}
__device__ __forceinline__ void unpack2(u64 v, float &a, float &b) {
    asm("mov.b64 {%0, %1}, %2;" : "=f"(a), "=f"(b) : "l"(v));
}
__device__ __forceinline__ u64 ffma2(u64 a, u64 b, u64 c) {
    u64 d; asm("fma.rn.f32x2 %0, %1, %2, %3;" : "=l"(d) : "l"(a), "l"(b), "l"(c));
    return d;
}
__device__ __forceinline__ u64 mul2(u64 a, u64 b) {
    u64 d; asm("mul.rn.f32x2 %0, %1, %2;" : "=l"(d) : "l"(a), "l"(b));
    return d;
}
__device__ __forceinline__ float frcp(float x) {
    float r; asm("rcp.approx.f32 %0, %1;" : "=f"(r) : "f"(x)); return r;
}

// Pre-transformed weights: row-paired u64 for direct f32x2 operands.
struct CWeights {
    ulonglong2 W2[2 * NIND][4];   // [k][q2]: rows (4q2..4q2+3) paired; k<32->Bmat, else Theta
    ulonglong2 L2[NIND][4];       // Lam
    ulonglong2 Off2[NDEP][4];     // column j, rows paired; +Gamma off-diag, 0 diag
    u64 Gd2[8];                   // (1+eps - Gamma_ii) pairs
    u64 Ups2[8];
};

__device__ CWeights g_scratch;    // written by prep kernel
__constant__ CWeights cw;         // copied from g_scratch before main kernel

// ---- prep kernel: transform raw weights into g_scratch layout ----
__global__ void prep_kernel(const float* __restrict__ Ups, const float* __restrict__ Bm,
                            const float* __restrict__ Th,  const float* __restrict__ Ga,
                            const float* __restrict__ La)
{
    const int tid = threadIdx.x;
    for (int idx = tid; idx < 2 * NIND * 8; idx += 64) {
        int k = idx >> 3, j2 = idx & 7;
        int r0 = 2 * j2, r1 = r0 + 1;
        float w0, w1;
        if (k < NIND) { w0 = Bm[r0 * NIND + k];          w1 = Bm[r1 * NIND + k]; }
        else          { w0 = Th[r0 * NIND + (k - NIND)]; w1 = Th[r1 * NIND + (k - NIND)]; }
        ((u64*)&g_scratch.W2[k][0])[j2] = pack2(w0, w1);
    }
    for (int idx = tid; idx < NIND * 8; idx += 64) {
        int k = idx >> 3, j2 = idx & 7;
        ((u64*)&g_scratch.L2[k][0])[j2] =
            pack2(La[(2 * j2) * NIND + k], La[(2 * j2 + 1) * NIND + k]);
    }
    for (int idx = tid; idx < NDEP * 8; idx += 64) {
        int j = idx >> 3, i2 = idx & 7;
        int i0 = 2 * i2, i1 = i0 + 1;
        float v0 = (i0 == j) ? 0.0f : Ga[i0 * NDEP + j];
        float v1 = (i1 == j) ? 0.0f : Ga[i1 * NDEP + j];
        ((u64*)&g_scratch.Off2[j][0])[i2] = pack2(v0, v1);
    }
    if (tid < 8) {
        g_scratch.Ups2[tid] = pack2(Ups[2 * tid], Ups[2 * tid + 1]);
        g_scratch.Gd2[tid]  = pack2(1.0f + EPSV - Ga[(2 * tid) * NDEP + 2 * tid],
                                    1.0f + EPSV - Ga[(2 * tid + 1) * NDEP + 2 * tid + 1]);
    }
}

#define S64   33   // u64 stride per staged row
#define YSTR  17   // u64 stride per element in the y-exchange buffer
#define TPB   128

// ROW-SPLIT WARP PAIRS: warp w handles rows 8h..8h+7 (h=w&1) of 2 elements.
// Halves all per-thread register state vs EPT=2 (the plateau cause) while
// keeping every weight address WARP-UNIFORM (constant-port broadcast intact).
// Row halves exchange y through smem each Neumann iteration (2 barriers/iter).
// All weights on the constant port (cheapest broadcast path, 2cyc/SM).
__global__ __launch_bounds__(TPB, 5)
void clefo_kernel(const float* __restrict__ X, const float* __restrict__ Z,
                  float* __restrict__ out)
{
    __shared__ u64 sStage[TPB * S64];   // X/Z slab (dup'd pairs); reused as sY

    const int tid = threadIdx.x;
    const int w   = tid >> 5, l = tid & 31;
    const int h   = w & 1;              // row half (warp-uniform!)
    const int g   = w >> 1;             // element group
    const int p0  = g * 64 + l;         // element A (block-local)
    const int p1  = p0 + 32;            // element B
    const size_t base = (size_t)blockIdx.x * TPB;

    // ---- stage X slab: coalesced float4 -> duplicated (x,x) u64 ----
    {
        const float4* src = (const float4*)(X + base * NIND);
#pragma unroll
        for (int i = 0; i < 8; ++i) {
            int idx = tid + TPB * i;
            float4 v = src[idx];
            u64* d = &sStage[(idx >> 3) * S64 + ((idx & 7) << 2)];
            d[0] = pack2(v.x, v.x); d[1] = pack2(v.y, v.y);
            d[2] = pack2(v.z, v.z); d[3] = pack2(v.w, v.w);
        }
    }
    __syncthreads();

    const u64* row0 = &sStage[p0 * S64];
    const u64* row1 = &sStage[p1 * S64];

    // ---- Phase 1a: own row-half of rhs (+Bm*x) and dd (=La*x), 2 elements
    u64 rhs0[4], rhs1[4], dd0[4], dd1[4];
#pragma unroll
    for (int i = 0; i < 4; ++i) {
        rhs0[i] = cw.Ups2[4 * h + i]; rhs1[i] = rhs0[i];
        dd0[i] = 0ull;                dd1[i] = 0ull;
    }
#pragma unroll
    for (int k = 0; k < NIND; ++k) {
        u64 x0 = row0[k], x1 = row1[k];
#pragma unroll
        for (int lq = 0; lq < 2; ++lq) {
            ulonglong2 w2 = cw.W2[k][2 * h + lq];      // warp-uniform LDC
            rhs0[2 * lq]     = ffma2(x0, w2.x, rhs0[2 * lq]);
            rhs0[2 * lq + 1] = ffma2(x0, w2.y, rhs0[2 * lq + 1]);
            rhs1[2 * lq]     = ffma2(x1, w2.x, rhs1[2 * lq]);
            rhs1[2 * lq + 1] = ffma2(x1, w2.y, rhs1[2 * lq + 1]);
            ulonglong2 l2 = cw.L2[k][2 * h + lq];
            dd0[2 * lq]      = ffma2(x0, l2.x, dd0[2 * lq]);
            dd0[2 * lq + 1]  = ffma2(x0, l2.y, dd0[2 * lq + 1]);
            dd1[2 * lq]      = ffma2(x1, l2.x, dd1[2 * lq]);
            dd1[2 * lq + 1]  = ffma2(x1, l2.y, dd1[2 * lq + 1]);
        }
    }
    __syncthreads();

    // ---- stage Z slab (reuse buffer) ----
    {
        const float4* src = (const float4*)(Z + base * NIND);
#pragma unroll
        for (int i = 0; i < 8; ++i) {
            int idx = tid + TPB * i;
            float4 v = src[idx];
            u64* d = &sStage[(idx >> 3) * S64 + ((idx & 7) << 2)];
            d[0] = pack2(v.x, v.x); d[1] = pack2(v.y, v.y);
            d[2] = pack2(v.z, v.z); d[3] = pack2(v.w, v.w);
        }
    }
    __syncthreads();

    // ---- Phase 1b: rhs += Theta*z (own half)
#pragma unroll
    for (int k = 0; k < NIND; ++k) {
        u64 x0 = row0[k], x1 = row1[k];
#pragma unroll
        for (int lq = 0; lq < 2; ++lq) {
            ulonglong2 w2 = cw.W2[NIND + k][2 * h + lq];
            rhs0[2 * lq]     = ffma2(x0, w2.x, rhs0[2 * lq]);
            rhs0[2 * lq + 1] = ffma2(x0, w2.y, rhs0[2 * lq + 1]);
            rhs1[2 * lq]     = ffma2(x1, w2.x, rhs1[2 * lq]);
            rhs1[2 * lq + 1] = ffma2(x1, w2.y, rhs1[2 * lq + 1]);
        }
    }
    __syncthreads();   // slab reads done; buffer becomes the y-exchange area

    // ---- Phase 2: inv = 1/(Gd - d) ; cc = inv*rhs (own half, 2 elements)
    u64 inv0[4], inv1[4], cc0[4], cc1[4];
#pragma unroll
    for (int i = 0; i < 4; ++i) {
        float g0, g1; unpack2(cw.Gd2[4 * h + i], g0, g1);
        float a0, a1; unpack2(dd0[i], a0, a1);
        inv0[i] = pack2(frcp(g0 - a0), frcp(g1 - a1));
        cc0[i]  = mul2(inv0[i], rhs0[i]);
        float b0, b1; unpack2(dd1[i], b0, b1);
        inv1[i] = pack2(frcp(g0 - b0), frcp(g1 - b1));
        cc1[i]  = mul2(inv1[i], rhs1[i]);
    }

    // ---- Publish y0 = cc as duplicated scalars: sY[elem][row] = (y,y)
    u64* sY = sStage;
#pragma unroll
    for (int i = 0; i < 4; ++i) {
        float a, b; unpack2(cc0[i], a, b);
        sY[p0 * YSTR + 8 * h + 2 * i]     = dup2(a);
        sY[p0 * YSTR + 8 * h + 2 * i + 1] = dup2(b);
        float c, d; unpack2(cc1[i], c, d);
        sY[p1 * YSTR + 8 * h + 2 * i]     = dup2(c);
        sY[p1 * YSTR + 8 * h + 2 * i + 1] = dup2(d);
    }
    __syncthreads();

    // ---- Phase 3: Neumann  y <- cc + inv*(GammaOff @ y), halves via smem
    u64 y0[4], y1[4];
#pragma unroll
    for (int it = 0; it < ITERS; ++it) {
        u64 acc0[4] = {0ull, 0ull, 0ull, 0ull};
        u64 acc1[4] = {0ull, 0ull, 0ull, 0ull};
#pragma unroll
        for (int j = 0; j < NDEP; ++j) {
            u64 yd0 = sY[p0 * YSTR + j];
            u64 yd1 = sY[p1 * YSTR + j];
#pragma unroll
            for (int lq = 0; lq < 2; ++lq) {
                ulonglong2 o = cw.Off2[j][2 * h + lq];   // warp-uniform LDC
                acc0[2 * lq]     = ffma2(yd0, o.x, acc0[2 * lq]);
                acc0[2 * lq + 1] = ffma2(yd0, o.y, acc0[2 * lq + 1]);
                acc1[2 * lq]     = ffma2(yd1, o.x, acc1[2 * lq]);
                acc1[2 * lq + 1] = ffma2(yd1, o.y, acc1[2 * lq + 1]);
            }
        }
#pragma unroll
        for (int i = 0; i < 4; ++i) {
            y0[i] = ffma2(inv0[i], acc0[i], cc0[i]);
            y1[i] = ffma2(inv1[i], acc1[i], cc1[i]);
        }
        if (it + 1 < ITERS) {
            __syncthreads();   // everyone done reading old y
#pragma unroll
            for (int i = 0; i < 4; ++i) {
                float a, b; unpack2(y0[i], a, b);
                sY[p0 * YSTR + 8 * h + 2 * i]     = dup2(a);
                sY[p0 * YSTR + 8 * h + 2 * i + 1] = dup2(b);
                float c, d; unpack2(y1[i], c, d);
                sY[p1 * YSTR + 8 * h + 2 * i]     = dup2(c);
                sY[p1 * YSTR + 8 * h + 2 * i + 1] = dup2(d);
            }
            __syncthreads();
        }
    }

    // ---- Store own half-rows of both elements (16B-aligned STG.128) ----
    ulonglong2* o0 = (ulonglong2*)(out + (base + p0) * NDEP + 8 * h);
    o0[0] = make_ulonglong2(y0[0], y0[1]);
    o0[1] = make_ulonglong2(y0[2], y0[3]);
    ulonglong2* o1 = (ulonglong2*)(out + (base + p1) * NDEP + 8 * h);
    o1[0] = make_ulonglong2(y1[0], y1[1]);
    o1[1] = make_ulonglong2(y1[2], y1[3]);
}

extern "C" void kernel_launch(void* const* d_in, const int* in_sizes, int n_in,
                              void* d_out, int out_size)
{
    const float* X  = (const float*)d_in[0];
    const float* Z  = (const float*)d_in[1];
    const float* Up = (const float*)d_in[2];
    const float* Bm = (const float*)d_in[3];
    const float* Th = (const float*)d_in[4];
    const float* Ga = (const float*)d_in[5];
    const float* La = (const float*)d_in[6];
    float* out = (float*)d_out;

    // 1) transform weights into device scratch
    prep_kernel<<<1, 64>>>(Up, Bm, Th, Ga, La);

    // 2) copy transformed weights into the constant bank (D2D, capturable)
    void* sp = nullptr;
    cudaGetSymbolAddress(&sp, g_scratch);
    cudaMemcpyToSymbolAsync(cw, sp, sizeof(CWeights), 0,
                            cudaMemcpyDeviceToDevice, 0);

    // 3) main kernel: 128 elements per 128-thread block (row-split warp pairs)
    const int blocks = BATCH / TPB;
    clefo_kernel<<<blocks, TPB>>>(X, Z, out);
}